// round 13
// baseline (speedup 1.0000x reference)
#include <cuda_runtime.h>
#include <cuda_bf16.h>
#include <cstdint>
#include <cstddef>

#define PB 256
#define PT 1024
#define PD 128
#define PH 256
#define BT (PB * PT)       // 262144 tokens
#define MT64 (BT / 64)     // 4096 64-row tiles (MLP kernels)
#define MT128 (BT / 128)   // 2048 128-row tiles (gate kernel)

// ---------------- scratch (device globals; no cudaMalloc allowed) ----------
__device__ __nv_bfloat16 g_gate[(size_t)BT * PH];  // gate bf16 (128 MB)
__device__ __nv_bfloat16 g_xb[(size_t)BT * 128];   // x in bf16
__device__ __nv_bfloat16 g_a[(size_t)BT * 128];    // MLP ping (padded)
__device__ __nv_bfloat16 g_b[(size_t)BT * 128];    // MLP pong
__device__ __nv_bfloat16 g_c[(size_t)BT * 64];     // layer-4 out (padded)
__device__ float g_pA[2048 * 256];                 // scan partials (fp32)
__device__ float g_pB[2048 * 256];

// padded, transposed ([N, K] K-major) bf16 weights
__device__ __nv_bfloat16 g_WxT[256 * 128];
__device__ __nv_bfloat16 g_W1T[128 * 128];
__device__ __nv_bfloat16 g_W2T[128 * 128];
__device__ __nv_bfloat16 g_W3T[128 * 128];
__device__ __nv_bfloat16 g_W4T[64 * 128];
__device__ __nv_bfloat16 g_W5T[256 * 64];
__device__ float g_b1p[128], g_b2p[128], g_b3p[128], g_b4p[64];

__device__ __forceinline__ float sigf(float x) { return 1.f / (1.f + __expf(-x)); }

__device__ __forceinline__ uint32_t smem_u32(const void* p) {
    uint32_t a;
    asm("{ .reg .u64 t; cvta.to.shared.u64 t, %1; cvt.u32.u64 %0, t; }" : "=r"(a) : "l"(p));
    return a;
}
__device__ __forceinline__ void cp16(uint32_t dst, const void* src) {
    asm volatile("cp.async.ca.shared.global [%0], [%1], 16;" :: "r"(dst), "l"(src) : "memory");
}
__device__ __forceinline__ void cp_commit() {
    asm volatile("cp.async.commit_group;" ::: "memory");
}
template <int N>
__device__ __forceinline__ void cp_wait() {
    asm volatile("cp.async.wait_group %0;" :: "n"(N) : "memory");
}
__device__ __forceinline__ void mma16(float* c, const uint32_t* a, uint32_t b0, uint32_t b1) {
    asm volatile(
        "mma.sync.aligned.m16n8k16.row.col.f32.bf16.bf16.f32 "
        "{%0,%1,%2,%3}, {%4,%5,%6,%7}, {%8,%9}, {%0,%1,%2,%3};"
        : "+f"(c[0]), "+f"(c[1]), "+f"(c[2]), "+f"(c[3])
        : "r"(a[0]), "r"(a[1]), "r"(a[2]), "r"(a[3]), "r"(b0), "r"(b1));
}
__device__ __forceinline__ void ldsm4(uint32_t* r, uint32_t addr) {
    asm volatile("ldmatrix.sync.aligned.m8n8.x4.shared.b16 {%0,%1,%2,%3}, [%4];"
                 : "=r"(r[0]), "=r"(r[1]), "=r"(r[2]), "=r"(r[3]) : "r"(addr));
}
__device__ __forceinline__ uint32_t ldu32(const __nv_bfloat16* p) {
    return *(const uint32_t*)p;
}

// ---------------- weight prep: transpose + pad + bf16 ----------------------
__global__ void prep_kernel(const float* __restrict__ Wx,
                            const float* __restrict__ W1, const float* __restrict__ b1,
                            const float* __restrict__ W2, const float* __restrict__ b2,
                            const float* __restrict__ W3, const float* __restrict__ b3,
                            const float* __restrict__ W4, const float* __restrict__ b4,
                            const float* __restrict__ W5)
{
    int t = blockIdx.x * blockDim.x + threadIdx.x;
    int S = gridDim.x * blockDim.x;
    for (int i = t; i < 256 * 128; i += S) { int n = i >> 7, k = i & 127; g_WxT[i] = __float2bfloat16(Wx[k * 256 + n]); }
    for (int i = t; i < 128 * 128; i += S) { int n = i >> 7, k = i & 127; g_W1T[i] = __float2bfloat16((n < 100) ? W1[k * 100 + n] : 0.f); }
    for (int i = t; i < 128 * 128; i += S) { int n = i >> 7, k = i & 127; g_W2T[i] = __float2bfloat16((n < 100 && k < 100) ? W2[k * 100 + n] : 0.f); }
    for (int i = t; i < 128 * 128; i += S) { int n = i >> 7, k = i & 127; g_W3T[i] = __float2bfloat16((n < 100 && k < 100) ? W3[k * 100 + n] : 0.f); }
    for (int i = t; i < 64 * 128;  i += S) { int n = i >> 7, k = i & 127; g_W4T[i] = __float2bfloat16((n < 50 && k < 100) ? W4[k * 50 + n] : 0.f); }
    for (int i = t; i < 256 * 64;  i += S) { int n = i >> 6, k = i & 63;  g_W5T[i] = __float2bfloat16((k < 50) ? W5[k * 256 + n] : 0.f); }
    for (int i = t; i < 128; i += S) {
        g_b1p[i] = (i < 100) ? b1[i] : 0.f;
        g_b2p[i] = (i < 100) ? b2[i] : 0.f;
        g_b3p[i] = (i < 100) ? b3[i] : 0.f;
    }
    for (int i = t; i < 64; i += S) g_b4p[i] = (i < 50) ? b4[i] : 0.f;
}

// ---------------- x -> bf16 -------------------------------------------------
__global__ void __launch_bounds__(256)
conv_x(const float* __restrict__ x, __nv_bfloat16* __restrict__ xb)
{
    size_t i = ((size_t)blockIdx.x * 256 + threadIdx.x) * 4;
    float4 v = *(const float4*)(x + i);
    __nv_bfloat162* o = (__nv_bfloat162*)(xb + i);
    o[0] = __floats2bfloat162_rn(v.x, v.y);
    o[1] = __floats2bfloat162_rn(v.z, v.w);
}

// ---------------- persistent bf16 GEMM (relu), M=64 tiles, 3 CTA/SM --------
// C[tile 64, BN] = relu(A[64, K] @ Bw[N, K]^T + bias); weights SMEM-resident.
// Warp grid 4m x 2n, warp tile 16 x (BN/2).
template <int K, int NFULL, int BN>
__global__ void __launch_bounds__(256, 3)
pgemm(const __nv_bfloat16* __restrict__ A, const __nv_bfloat16* __restrict__ Bw,
      const float* __restrict__ bias, __nv_bfloat16* __restrict__ C)
{
    constexpr int PITCH = K + 8;
    constexpr int WELEM = BN * PITCH;
    constexpr int ASTAGE = 64 * PITCH;
    constexpr int WN = BN / 2;
    constexpr int NT = WN / 8;
    extern __shared__ __nv_bfloat16 smb[];
    const uint32_t sbase = smem_u32(smb);

    const int tid = threadIdx.x;
    const int lane = tid & 31, wid = tid >> 5;
    const int gq = lane >> 2, tig = lane & 3;
    const int wm = wid & 3, wn = wid >> 2;          // 4m x 2n
    const int colBase = blockIdx.x * BN;
    const int t0 = blockIdx.y, stride = gridDim.y;

    const int lrow = ((lane >> 3) & 1) * 8 + (lane & 7);
    const int lcol = (lane >> 4) * 8;
    const uint32_t aOffL = (uint32_t)((wm * 16 + lrow) * PITCH + lcol) * 2u;
    const uint32_t bBase = sbase + (uint32_t)((wn * WN + lrow) * PITCH + lcol) * 2u;

    // resident weights (group 0)
    for (int id = tid; id < BN * (K / 8); id += 256) {
        int r = id / (K / 8), sg = (id % (K / 8)) * 8;
        cp16(sbase + (uint32_t)(r * PITCH + sg) * 2u, Bw + (size_t)(colBase + r) * K + sg);
    }
    cp_commit();

    auto loadA = [&](int tile, int buf) {
        if (tile < MT64) {
            const size_t rb = (size_t)tile * 64;
            #pragma unroll
            for (int it = 0; it < (K / 8) * 64 / 256; it++) {
                int id = tid + it * 256;
                int r = id / (K / 8), sg = (id % (K / 8)) * 8;
                cp16(sbase + (uint32_t)(WELEM + buf * ASTAGE + r * PITCH + sg) * 2u,
                     A + (rb + r) * K + sg);
            }
        }
        cp_commit();
    };
    loadA(t0, 0);
    loadA(t0 + stride, 1);

    for (int t = t0, it = 0; t < MT64; t += stride, it++) {
        cp_wait<1>();
        __syncthreads();
        const uint32_t aBase = sbase + (uint32_t)(WELEM + (it & 1) * ASTAGE) * 2u + aOffL;

        float acc[NT][4];
        #pragma unroll
        for (int nt = 0; nt < NT; nt++)
            #pragma unroll
            for (int j = 0; j < 4; j++) acc[nt][j] = 0.f;

        #pragma unroll
        for (int s = 0; s < K / 16; s++) {
            const uint32_t k2 = (uint32_t)(s * 16) * 2u;
            uint32_t af[4];
            ldsm4(af, aBase + k2);
            #pragma unroll
            for (int p = 0; p < NT / 2; p++) {
                uint32_t bf[4];
                ldsm4(bf, bBase + (uint32_t)(p * 16 * PITCH) * 2u + k2);
                mma16(acc[2 * p],     af, bf[0], bf[2]);
                mma16(acc[2 * p + 1], af, bf[1], bf[3]);
            }
        }
        __syncthreads();
        loadA(t + 2 * stride, it & 1);    // prefetch overlaps epilogue

        const size_t rowBase = (size_t)t * 64;
        #pragma unroll
        for (int nt = 0; nt < NT; nt++) {
            const int c0 = colBase + wn * WN + nt * 8 + 2 * tig;
            const float q0 = __ldg(bias + c0), q1 = __ldg(bias + c0 + 1);
            #pragma unroll
            for (int h = 0; h < 2; h++) {
                const size_t r = rowBase + wm * 16 + gq + h * 8;
                float v0 = fmaxf(acc[nt][2 * h + 0] + q0, 0.f);
                float v1 = fmaxf(acc[nt][2 * h + 1] + q1, 0.f);
                *(__nv_bfloat162*)(C + r * NFULL + c0) = __floats2bfloat162_rn(v0, v1);
            }
        }
    }
}

// ---------------- persistent fused gate GEMM (scalar frag loads, R9) --------
// gate[:, half*128 + 0..127] = sigmoid(vc@W5h + b5) * sigmoid(xb@Wxh + bx)
__global__ void __launch_bounds__(512, 1)
pgate(const __nv_bfloat16* __restrict__ xb, const __nv_bfloat16* __restrict__ WxT,
      const float* __restrict__ bx,
      const __nv_bfloat16* __restrict__ vc, const __nv_bfloat16* __restrict__ W5T,
      const float* __restrict__ b5, __nv_bfloat16* __restrict__ C)
{
    constexpr int PX = 136, PV = 72;
    constexpr int WX = 0;
    constexpr int W5 = 128 * PX;
    constexpr int XB0 = W5 + 128 * PV;
    constexpr int XB1 = XB0 + 128 * PX;
    constexpr int VC0 = XB1 + 128 * PX;
    constexpr int VC1 = VC0 + 128 * PV;
    extern __shared__ __nv_bfloat16 smb[];
    const uint32_t sbase = smem_u32(smb);

    const int tid = threadIdx.x;
    const int lane = tid & 31, wid = tid >> 5;
    const int gq = lane >> 2, tig = lane & 3;
    const int wm = wid & 3, wn = wid >> 2;
    const int half = blockIdx.x;
    const int t0 = blockIdx.y, stride = gridDim.y;

    for (int id = tid; id < 128 * 16; id += 512) {
        int r = id >> 4, sg = (id & 15) * 8;
        cp16(sbase + (uint32_t)(WX + r * PX + sg) * 2u,
             WxT + (size_t)(half * 128 + r) * 128 + sg);
    }
    cp_commit();
    for (int id = tid; id < 128 * 8; id += 512) {
        int r = id >> 3, sg = (id & 7) * 8;
        cp16(sbase + (uint32_t)(W5 + r * PV + sg) * 2u,
             W5T + (size_t)(half * 128 + r) * 64 + sg);
    }
    cp_commit();

    auto load_stage = [&](int tile, int buf) {
        if (tile < MT128) {
            const size_t rb = (size_t)tile * 128;
            const int xoff = buf ? XB1 : XB0;
            const int voff = buf ? VC1 : VC0;
            #pragma unroll
            for (int it = 0; it < 4; it++) {
                int id = tid + it * 512;
                int r = id >> 4, sg = (id & 15) * 8;
                cp16(sbase + (uint32_t)(xoff + r * PX + sg) * 2u, xb + (rb + r) * 128 + sg);
            }
            #pragma unroll
            for (int it = 0; it < 2; it++) {
                int id = tid + it * 512;
                int r = id >> 3, sg = (id & 7) * 8;
                cp16(sbase + (uint32_t)(voff + r * PV + sg) * 2u, vc + (rb + r) * 64 + sg);
            }
        }
        cp_commit();
    };
    load_stage(t0, 0);
    load_stage(t0 + stride, 1);

    float hbx[4][2], hb5[4][2];
    #pragma unroll
    for (int nt = 0; nt < 4; nt++) {
        const int cg = half * 128 + wn * 32 + nt * 8 + 2 * tig;
        hbx[nt][0] = __ldg(bx + cg); hbx[nt][1] = __ldg(bx + cg + 1);
        hb5[nt][0] = __ldg(b5 + cg); hb5[nt][1] = __ldg(b5 + cg + 1);
    }

    for (int t = t0, it = 0; t < MT128; t += stride, it++) {
        cp_wait<1>();
        __syncthreads();
        const __nv_bfloat16* Xs = smb + (it & 1 ? XB1 : XB0);
        const __nv_bfloat16* Vs = smb + (it & 1 ? VC1 : VC0);

        float lin[2][4][4], fx[2][4][4];
        #pragma unroll
        for (int mt = 0; mt < 2; mt++)
            #pragma unroll
            for (int nt = 0; nt < 4; nt++)
                #pragma unroll
                for (int j = 0; j < 4; j++) { lin[mt][nt][j] = 0.f; fx[mt][nt][j] = 0.f; }

        #pragma unroll
        for (int s = 0; s < 8; s++) {
            const int k0 = s * 16;
            uint32_t af[2][4];
            #pragma unroll
            for (int mt = 0; mt < 2; mt++) {
                const __nv_bfloat16* ap = Xs + (wm * 32 + mt * 16 + gq) * PX + k0 + 2 * tig;
                af[mt][0] = ldu32(ap);
                af[mt][1] = ldu32(ap + 8 * PX);
                af[mt][2] = ldu32(ap + 8);
                af[mt][3] = ldu32(ap + 8 * PX + 8);
            }
            #pragma unroll
            for (int nt = 0; nt < 4; nt++) {
                const __nv_bfloat16* bp = smb + WX + (wn * 32 + nt * 8 + gq) * PX + k0 + 2 * tig;
                uint32_t b0 = ldu32(bp);
                uint32_t b1 = ldu32(bp + 8);
                mma16(lin[0][nt], af[0], b0, b1);
                mma16(lin[1][nt], af[1], b0, b1);
            }
        }
        #pragma unroll
        for (int s = 0; s < 4; s++) {
            const int k0 = s * 16;
            uint32_t af[2][4];
            #pragma unroll
            for (int mt = 0; mt < 2; mt++) {
                const __nv_bfloat16* ap = Vs + (wm * 32 + mt * 16 + gq) * PV + k0 + 2 * tig;
                af[mt][0] = ldu32(ap);
                af[mt][1] = ldu32(ap + 8 * PV);
                af[mt][2] = ldu32(ap + 8);
                af[mt][3] = ldu32(ap + 8 * PV + 8);
            }
            #pragma unroll
            for (int nt = 0; nt < 4; nt++) {
                const __nv_bfloat16* bp = smb + W5 + (wn * 32 + nt * 8 + gq) * PV + k0 + 2 * tig;
                uint32_t b0 = ldu32(bp);
                uint32_t b1 = ldu32(bp + 8);
                mma16(fx[0][nt], af[0], b0, b1);
                mma16(fx[1][nt], af[1], b0, b1);
            }
        }
        __syncthreads();
        load_stage(t + 2 * stride, it & 1);

        const size_t rowBase = (size_t)t * 128;
        #pragma unroll
        for (int mt = 0; mt < 2; mt++)
            #pragma unroll
            for (int nt = 0; nt < 4; nt++) {
                const int cg = half * 128 + wn * 32 + nt * 8 + 2 * tig;
                #pragma unroll
                for (int h = 0; h < 2; h++) {
                    const size_t r = rowBase + wm * 32 + mt * 16 + gq + h * 8;
                    float v0 = sigf(fx[mt][nt][2 * h + 0] + hb5[nt][0]) * sigf(lin[mt][nt][2 * h + 0] + hbx[nt][0]);
                    float v1 = sigf(fx[mt][nt][2 * h + 1] + hb5[nt][1]) * sigf(lin[mt][nt][2 * h + 1] + hbx[nt][1]);
                    *(__nv_bfloat162*)(C + r * PH + cg) = __floats2bfloat162_rn(v0, v1);
                }
            }
    }
}

// ---------------- scan as max-plus reduction --------------------------------
__global__ void __launch_bounds__(256)
scan_part(const __nv_bfloat16* __restrict__ gate, float* __restrict__ pA, float* __restrict__ pB)
{
    const int b = blockIdx.x >> 3, c = blockIdx.x & 7;
    const int i = threadIdx.x;
    const __nv_bfloat16* gb = gate + ((size_t)b << 18);
    float Aacc = 0.f, Bacc = -3.0e38f;
    const int t0 = c * 128;
    #pragma unroll 8
    for (int t = t0; t < t0 + 128; t++) {
        float val = __bfloat162float(gb[(size_t)t * 256 + ((i + t + 1) & 255)]);
        Aacc += val;
        Bacc = fmaxf(Bacc + val, 0.f);
    }
    const int o = blockIdx.x * 256 + i;
    pA[o] = Aacc;
    pB[o] = Bacc;
}

__global__ void __launch_bounds__(256)
scan_fin(const float* __restrict__ pA, const float* __restrict__ pB,
         const float* __restrict__ Wo, const float* __restrict__ bo,
         float* __restrict__ out)
{
    const int b = blockIdx.x, i = threadIdx.x;
    float A = 0.f, B = -3.0e38f;
    #pragma unroll
    for (int c = 0; c < 8; c++) {
        const int o = (b * 8 + c) * 256 + i;
        float Ac = pA[o], Bc = pB[o];
        B = fmaxf(B + Ac, Bc);
        A += Ac;
    }
    const float v = fmaxf(A, B);
    out[PB + (size_t)b * 256 + i] = v;

    __shared__ float sh[256];
    sh[i] = v * Wo[i];
    __syncthreads();
    #pragma unroll
    for (int s = 128; s > 0; s >>= 1) {
        if (i < s) sh[i] += sh[i + s];
        __syncthreads();
    }
    if (i == 0) out[b] = 1.f / (1.f + __expf(-(sh[0] + bo[0])));
}

// ---------------- launch ---------------------------------------------------
extern "C" void kernel_launch(void* const* d_in, const int* in_sizes, int n_in,
                              void* d_out, int out_size)
{
    const float* x  = (const float*)d_in[0];
    const float* Wx = (const float*)d_in[1];
    const float* bx = (const float*)d_in[2];
    const float* W1 = (const float*)d_in[3];
    const float* b1 = (const float*)d_in[4];
    const float* W2 = (const float*)d_in[5];
    const float* b2 = (const float*)d_in[6];
    const float* W3 = (const float*)d_in[7];
    const float* b3 = (const float*)d_in[8];
    const float* W4 = (const float*)d_in[9];
    const float* b4 = (const float*)d_in[10];
    const float* W5 = (const float*)d_in[11];
    const float* b5 = (const float*)d_in[12];
    const float* Wo = (const float*)d_in[13];
    const float* bo = (const float*)d_in[14];
    float* out = (float*)d_out;

    void *p_gate, *p_xb, *p_a, *p_b, *p_c, *p_pA, *p_pB;
    void *p_WxT, *p_W1T, *p_W2T, *p_W3T, *p_W4T, *p_W5T;
    void *p_b1p, *p_b2p, *p_b3p, *p_b4p;
    cudaGetSymbolAddress(&p_gate, g_gate);
    cudaGetSymbolAddress(&p_xb, g_xb);
    cudaGetSymbolAddress(&p_a, g_a);
    cudaGetSymbolAddress(&p_b, g_b);
    cudaGetSymbolAddress(&p_c, g_c);
    cudaGetSymbolAddress(&p_pA, g_pA);
    cudaGetSymbolAddress(&p_pB, g_pB);
    cudaGetSymbolAddress(&p_WxT, g_WxT);
    cudaGetSymbolAddress(&p_W1T, g_W1T);
    cudaGetSymbolAddress(&p_W2T, g_W2T);
    cudaGetSymbolAddress(&p_W3T, g_W3T);
    cudaGetSymbolAddress(&p_W4T, g_W4T);
    cudaGetSymbolAddress(&p_W5T, g_W5T);
    cudaGetSymbolAddress(&p_b1p, g_b1p);
    cudaGetSymbolAddress(&p_b2p, g_b2p);
    cudaGetSymbolAddress(&p_b3p, g_b3p);
    cudaGetSymbolAddress(&p_b4p, g_b4p);
    __nv_bfloat16* gate = (__nv_bfloat16*)p_gate;
    __nv_bfloat16* xb   = (__nv_bfloat16*)p_xb;
    __nv_bfloat16* va   = (__nv_bfloat16*)p_a;
    __nv_bfloat16* vb   = (__nv_bfloat16*)p_b;
    __nv_bfloat16* vc   = (__nv_bfloat16*)p_c;

    // smem sizes (bytes)
    constexpr int S_P128 = (128 * 136 + 2 * 64 * 136) * 2;    // 69632  (3 CTA/SM)
    constexpr int S_P64  = (64 * 136 + 2 * 64 * 136) * 2;     // 52224
    constexpr int S_GATE = (128 * 136 + 128 * 72 + 2 * 128 * 136 + 2 * 128 * 72) * 2;  // 159744
    cudaFuncSetAttribute(pgemm<128, 128, 128>, cudaFuncAttributeMaxDynamicSharedMemorySize, S_P128);
    cudaFuncSetAttribute(pgemm<128, 64, 64>,   cudaFuncAttributeMaxDynamicSharedMemorySize, S_P64);
    cudaFuncSetAttribute(pgate, cudaFuncAttributeMaxDynamicSharedMemorySize, S_GATE);

    prep_kernel<<<128, 256>>>(Wx, W1, b1, W2, b2, W3, b3, W4, b4, W5);
    conv_x<<<BT * 128 / (256 * 4), 256>>>(x, xb);

    // persistent MLP chain (M=64 tiles, 3 CTAs/SM)
    pgemm<128, 128, 128><<<dim3(1, 444), 256, S_P128>>>(xb, (const __nv_bfloat16*)p_W1T, (const float*)p_b1p, va);
    pgemm<128, 128, 128><<<dim3(1, 444), 256, S_P128>>>(va, (const __nv_bfloat16*)p_W2T, (const float*)p_b2p, vb);
    pgemm<128, 128, 128><<<dim3(1, 444), 256, S_P128>>>(vb, (const __nv_bfloat16*)p_W3T, (const float*)p_b3p, va);
    pgemm<128, 64, 64><<<dim3(1, 444), 256, S_P64>>>(va, (const __nv_bfloat16*)p_W4T, (const float*)p_b4p, vc);
    // persistent fused gate
    pgate<<<dim3(2, 74), 512, S_GATE>>>(xb, (const __nv_bfloat16*)p_WxT, bx,
                                        vc, (const __nv_bfloat16*)p_W5T, b5, gate);
    // scan as parallel reduction + output head
    scan_part<<<PB * 8, 256>>>(gate, (float*)p_pA, (float*)p_pB);
    scan_fin<<<PB, 256>>>((const float*)p_pA, (const float*)p_pB, Wo, bo, out);
}

// round 15
// speedup vs baseline: 1.1680x; 1.1680x over previous
#include <cuda_runtime.h>
#include <cuda_bf16.h>
#include <cstdint>
#include <cstddef>

#define PB 256
#define PT 1024
#define PD 128
#define PH 256
#define BT (PB * PT)       // 262144 tokens
#define MT64 (BT / 64)     // 4096 64-row tiles (fused MLP kernels)
#define MT128 (BT / 128)   // 2048 128-row tiles (gate kernel)

// ---------------- scratch (device globals; no cudaMalloc allowed) ----------
__device__ __nv_bfloat16 g_gate[(size_t)BT * PH];  // gate bf16 (128 MB)
__device__ __nv_bfloat16 g_xb[(size_t)BT * 128];   // x in bf16
__device__ __nv_bfloat16 g_b[(size_t)BT * 128];    // L2 out (padded)
__device__ __nv_bfloat16 g_c[(size_t)BT * 64];     // L4 out (padded)
__device__ float g_pA[2048 * 256];                 // scan partials (fp32)
__device__ float g_pB[2048 * 256];

// padded, transposed ([N, K] K-major) bf16 weights
__device__ __nv_bfloat16 g_WxT[256 * 128];
__device__ __nv_bfloat16 g_W1T[128 * 128];
__device__ __nv_bfloat16 g_W2T[128 * 128];
__device__ __nv_bfloat16 g_W3T[128 * 128];
__device__ __nv_bfloat16 g_W4T[64 * 128];
__device__ __nv_bfloat16 g_W5T[256 * 64];
__device__ float g_b1p[128], g_b2p[128], g_b3p[128], g_b4p[64];

__device__ __forceinline__ float sigf(float x) { return 1.f / (1.f + __expf(-x)); }

__device__ __forceinline__ uint32_t smem_u32(const void* p) {
    uint32_t a;
    asm("{ .reg .u64 t; cvta.to.shared.u64 t, %1; cvt.u32.u64 %0, t; }" : "=r"(a) : "l"(p));
    return a;
}
__device__ __forceinline__ void cp16(uint32_t dst, const void* src) {
    asm volatile("cp.async.ca.shared.global [%0], [%1], 16;" :: "r"(dst), "l"(src) : "memory");
}
__device__ __forceinline__ void cp_commit() {
    asm volatile("cp.async.commit_group;" ::: "memory");
}
template <int N>
__device__ __forceinline__ void cp_wait() {
    asm volatile("cp.async.wait_group %0;" :: "n"(N) : "memory");
}
__device__ __forceinline__ void mma16(float* c, const uint32_t* a, uint32_t b0, uint32_t b1) {
    asm volatile(
        "mma.sync.aligned.m16n8k16.row.col.f32.bf16.bf16.f32 "
        "{%0,%1,%2,%3}, {%4,%5,%6,%7}, {%8,%9}, {%0,%1,%2,%3};"
        : "+f"(c[0]), "+f"(c[1]), "+f"(c[2]), "+f"(c[3])
        : "r"(a[0]), "r"(a[1]), "r"(a[2]), "r"(a[3]), "r"(b0), "r"(b1));
}
__device__ __forceinline__ void ldsm4(uint32_t* r, uint32_t addr) {
    asm volatile("ldmatrix.sync.aligned.m8n8.x4.shared.b16 {%0,%1,%2,%3}, [%4];"
                 : "=r"(r[0]), "=r"(r[1]), "=r"(r[2]), "=r"(r[3]) : "r"(addr));
}
__device__ __forceinline__ uint32_t ldu32(const __nv_bfloat16* p) {
    return *(const uint32_t*)p;
}

// ---------------- weight prep: transpose + pad + bf16 ----------------------
__global__ void prep_kernel(const float* __restrict__ Wx,
                            const float* __restrict__ W1, const float* __restrict__ b1,
                            const float* __restrict__ W2, const float* __restrict__ b2,
                            const float* __restrict__ W3, const float* __restrict__ b3,
                            const float* __restrict__ W4, const float* __restrict__ b4,
                            const float* __restrict__ W5)
{
    int t = blockIdx.x * blockDim.x + threadIdx.x;
    int S = gridDim.x * blockDim.x;
    for (int i = t; i < 256 * 128; i += S) { int n = i >> 7, k = i & 127; g_WxT[i] = __float2bfloat16(Wx[k * 256 + n]); }
    for (int i = t; i < 128 * 128; i += S) { int n = i >> 7, k = i & 127; g_W1T[i] = __float2bfloat16((n < 100) ? W1[k * 100 + n] : 0.f); }
    for (int i = t; i < 128 * 128; i += S) { int n = i >> 7, k = i & 127; g_W2T[i] = __float2bfloat16((n < 100 && k < 100) ? W2[k * 100 + n] : 0.f); }
    for (int i = t; i < 128 * 128; i += S) { int n = i >> 7, k = i & 127; g_W3T[i] = __float2bfloat16((n < 100 && k < 100) ? W3[k * 100 + n] : 0.f); }
    for (int i = t; i < 64 * 128;  i += S) { int n = i >> 7, k = i & 127; g_W4T[i] = __float2bfloat16((n < 50 && k < 100) ? W4[k * 50 + n] : 0.f); }
    for (int i = t; i < 256 * 64;  i += S) { int n = i >> 6, k = i & 63;  g_W5T[i] = __float2bfloat16((k < 50) ? W5[k * 256 + n] : 0.f); }
    for (int i = t; i < 128; i += S) {
        g_b1p[i] = (i < 100) ? b1[i] : 0.f;
        g_b2p[i] = (i < 100) ? b2[i] : 0.f;
        g_b3p[i] = (i < 100) ? b3[i] : 0.f;
    }
    for (int i = t; i < 64; i += S) g_b4p[i] = (i < 50) ? b4[i] : 0.f;
}

// ---------------- x -> bf16 -------------------------------------------------
__global__ void __launch_bounds__(256)
conv_x(const float* __restrict__ x, __nv_bfloat16* __restrict__ xb)
{
    size_t i = ((size_t)blockIdx.x * 256 + threadIdx.x) * 4;
    float4 v = *(const float4*)(x + i);
    __nv_bfloat162* o = (__nv_bfloat162*)(xb + i);
    o[0] = __floats2bfloat162_rn(v.x, v.y);
    o[1] = __floats2bfloat162_rn(v.z, v.w);
}

// ---------------- fused two-layer persistent GEMM ---------------------------
// Per 64-row tile: H = relu(A@W1^T + b1) kept in SMEM; C = relu(H@W2^T + b2).
// Both K dims = 128 (padded). Weights SMEM-resident. A single-buffered; the
// next tile's A load is issued right after H is built, overlapping gemm2.
// 8 warps, grid 4m x 2n; warp tile 16 x (N/2).
template <int N2, int NFULL2>
__global__ void __launch_bounds__(256, 2)
pfused(const __nv_bfloat16* __restrict__ A,
       const __nv_bfloat16* __restrict__ W1g, const float* __restrict__ b1v,
       const __nv_bfloat16* __restrict__ W2g, const float* __restrict__ b2v,
       __nv_bfloat16* __restrict__ C)
{
    constexpr int PITCH = 136;
    constexpr int K = 128, N1 = 128;
    constexpr int W1O = 0;
    constexpr int W2O = N1 * PITCH;               // 17408
    constexpr int AO  = W2O + N2 * PITCH;
    constexpr int HO  = AO + 64 * PITCH;
    constexpr int NT2 = (N2 / 2) / 8;
    extern __shared__ __nv_bfloat16 smb[];
    const uint32_t sbase = smem_u32(smb);

    const int tid = threadIdx.x;
    const int lane = tid & 31, wid = tid >> 5;
    const int gq = lane >> 2, tig = lane & 3;
    const int wm = wid & 3, wn = wid >> 2;        // 4m x 2n
    const int t0 = blockIdx.x, stride = gridDim.x;

    const int lrow = ((lane >> 3) & 1) * 8 + (lane & 7);
    const int lcol = (lane >> 4) * 8;
    const uint32_t aOff = (uint32_t)((wm * 16 + lrow) * PITCH + lcol) * 2u;   // A and H
    const uint32_t b1Base = sbase + (uint32_t)(W1O + (wn * 64 + lrow) * PITCH + lcol) * 2u;
    const uint32_t b2Base = sbase + (uint32_t)(W2O + (wn * (N2 / 2) + lrow) * PITCH + lcol) * 2u;

    // resident weights (one commit group)
    for (int id = tid; id < N1 * 16; id += 256) {
        int r = id >> 4, sg = (id & 15) * 8;
        cp16(sbase + (uint32_t)(W1O + r * PITCH + sg) * 2u, W1g + (size_t)r * K + sg);
    }
    for (int id = tid; id < N2 * 16; id += 256) {
        int r = id >> 4, sg = (id & 15) * 8;
        cp16(sbase + (uint32_t)(W2O + r * PITCH + sg) * 2u, W2g + (size_t)r * 128 + sg);
    }
    cp_commit();

    auto loadA = [&](int tile) {
        if (tile < MT64) {
            const size_t rb = (size_t)tile * 64;
            #pragma unroll
            for (int it = 0; it < 4; it++) {      // 64 rows x 16 segs
                int id = tid + it * 256;
                int r = id >> 4, sg = (id & 15) * 8;
                cp16(sbase + (uint32_t)(AO + r * PITCH + sg) * 2u, A + (rb + r) * K + sg);
            }
        }
        cp_commit();
    };
    loadA(t0);

    float acc[8][4];

    for (int t = t0; t < MT64; t += stride) {
        cp_wait<0>();
        __syncthreads();                          // A(t) ready; prev-tile H reads done

        // ---- gemm1: acc = A @ W1 (K=128), warp tile 16x64 -----------------
        #pragma unroll
        for (int nt = 0; nt < 8; nt++)
            #pragma unroll
            for (int j = 0; j < 4; j++) acc[nt][j] = 0.f;
        const uint32_t aBase = sbase + (uint32_t)AO * 2u + aOff;
        #pragma unroll
        for (int s = 0; s < 8; s++) {
            const uint32_t k2 = (uint32_t)(s * 16) * 2u;
            uint32_t af[4];
            ldsm4(af, aBase + k2);
            #pragma unroll
            for (int p = 0; p < 4; p++) {
                uint32_t bf[4];
                ldsm4(bf, b1Base + (uint32_t)(p * 16 * PITCH) * 2u + k2);
                mma16(acc[2 * p],     af, bf[0], bf[2]);
                mma16(acc[2 * p + 1], af, bf[1], bf[3]);
            }
        }
        // H = relu(acc + b1) -> SMEM (bank-clean: 4*gq+tig covers all banks)
        #pragma unroll
        for (int nt = 0; nt < 8; nt++) {
            const int c0 = wn * 64 + nt * 8 + 2 * tig;
            const float q0 = __ldg(b1v + c0), q1 = __ldg(b1v + c0 + 1);
            #pragma unroll
            for (int h = 0; h < 2; h++) {
                const int r = wm * 16 + gq + h * 8;
                float v0 = fmaxf(acc[nt][2 * h + 0] + q0, 0.f);
                float v1 = fmaxf(acc[nt][2 * h + 1] + q1, 0.f);
                *(__nv_bfloat162*)(smb + HO + r * PITCH + c0) = __floats2bfloat162_rn(v0, v1);
            }
        }
        __syncthreads();                          // A consumed + H visible
        loadA(t + stride);                        // overlaps gemm2 + epilogue

        // ---- gemm2: acc = H @ W2 (K=128), warp tile 16x(N2/2) -------------
        #pragma unroll
        for (int nt = 0; nt < NT2; nt++)
            #pragma unroll
            for (int j = 0; j < 4; j++) acc[nt][j] = 0.f;
        const uint32_t hBase = sbase + (uint32_t)HO * 2u + aOff;
        #pragma unroll
        for (int s = 0; s < 8; s++) {
            const uint32_t k2 = (uint32_t)(s * 16) * 2u;
            uint32_t af[4];
            ldsm4(af, hBase + k2);
            #pragma unroll
            for (int p = 0; p < NT2 / 2; p++) {
                uint32_t bf[4];
                ldsm4(bf, b2Base + (uint32_t)(p * 16 * PITCH) * 2u + k2);
                mma16(acc[2 * p],     af, bf[0], bf[2]);
                mma16(acc[2 * p + 1], af, bf[1], bf[3]);
            }
        }
        // C = relu(acc + b2) -> global
        const size_t rowBase = (size_t)t * 64;
        #pragma unroll
        for (int nt = 0; nt < NT2; nt++) {
            const int c0 = wn * (N2 / 2) + nt * 8 + 2 * tig;
            const float q0 = __ldg(b2v + c0), q1 = __ldg(b2v + c0 + 1);
            #pragma unroll
            for (int h = 0; h < 2; h++) {
                const size_t r = rowBase + wm * 16 + gq + h * 8;
                float v0 = fmaxf(acc[nt][2 * h + 0] + q0, 0.f);
                float v1 = fmaxf(acc[nt][2 * h + 1] + q1, 0.f);
                *(__nv_bfloat162*)(C + r * NFULL2 + c0) = __floats2bfloat162_rn(v0, v1);
            }
        }
    }
}

// ---------------- persistent fused gate GEMM (R9 scalar version) ------------
__global__ void __launch_bounds__(512, 1)
pgate(const __nv_bfloat16* __restrict__ xb, const __nv_bfloat16* __restrict__ WxT,
      const float* __restrict__ bx,
      const __nv_bfloat16* __restrict__ vc, const __nv_bfloat16* __restrict__ W5T,
      const float* __restrict__ b5, __nv_bfloat16* __restrict__ C)
{
    constexpr int PX = 136, PV = 72;
    constexpr int WX = 0;
    constexpr int W5 = 128 * PX;
    constexpr int XB0 = W5 + 128 * PV;
    constexpr int XB1 = XB0 + 128 * PX;
    constexpr int VC0 = XB1 + 128 * PX;
    constexpr int VC1 = VC0 + 128 * PV;
    extern __shared__ __nv_bfloat16 smb[];
    const uint32_t sbase = smem_u32(smb);

    const int tid = threadIdx.x;
    const int lane = tid & 31, wid = tid >> 5;
    const int gq = lane >> 2, tig = lane & 3;
    const int wm = wid & 3, wn = wid >> 2;
    const int half = blockIdx.x;
    const int t0 = blockIdx.y, stride = gridDim.y;

    for (int id = tid; id < 128 * 16; id += 512) {
        int r = id >> 4, sg = (id & 15) * 8;
        cp16(sbase + (uint32_t)(WX + r * PX + sg) * 2u,
             WxT + (size_t)(half * 128 + r) * 128 + sg);
    }
    cp_commit();
    for (int id = tid; id < 128 * 8; id += 512) {
        int r = id >> 3, sg = (id & 7) * 8;
        cp16(sbase + (uint32_t)(W5 + r * PV + sg) * 2u,
             W5T + (size_t)(half * 128 + r) * 64 + sg);
    }
    cp_commit();

    auto load_stage = [&](int tile, int buf) {
        if (tile < MT128) {
            const size_t rb = (size_t)tile * 128;
            const int xoff = buf ? XB1 : XB0;
            const int voff = buf ? VC1 : VC0;
            #pragma unroll
            for (int it = 0; it < 4; it++) {
                int id = tid + it * 512;
                int r = id >> 4, sg = (id & 15) * 8;
                cp16(sbase + (uint32_t)(xoff + r * PX + sg) * 2u, xb + (rb + r) * 128 + sg);
            }
            #pragma unroll
            for (int it = 0; it < 2; it++) {
                int id = tid + it * 512;
                int r = id >> 3, sg = (id & 7) * 8;
                cp16(sbase + (uint32_t)(voff + r * PV + sg) * 2u, vc + (rb + r) * 64 + sg);
            }
        }
        cp_commit();
    };
    load_stage(t0, 0);
    load_stage(t0 + stride, 1);

    float hbx[4][2], hb5[4][2];
    #pragma unroll
    for (int nt = 0; nt < 4; nt++) {
        const int cg = half * 128 + wn * 32 + nt * 8 + 2 * tig;
        hbx[nt][0] = __ldg(bx + cg); hbx[nt][1] = __ldg(bx + cg + 1);
        hb5[nt][0] = __ldg(b5 + cg); hb5[nt][1] = __ldg(b5 + cg + 1);
    }

    for (int t = t0, it = 0; t < MT128; t += stride, it++) {
        cp_wait<1>();
        __syncthreads();
        const __nv_bfloat16* Xs = smb + (it & 1 ? XB1 : XB0);
        const __nv_bfloat16* Vs = smb + (it & 1 ? VC1 : VC0);

        float lin[2][4][4], fx[2][4][4];
        #pragma unroll
        for (int mt = 0; mt < 2; mt++)
            #pragma unroll
            for (int nt = 0; nt < 4; nt++)
                #pragma unroll
                for (int j = 0; j < 4; j++) { lin[mt][nt][j] = 0.f; fx[mt][nt][j] = 0.f; }

        #pragma unroll
        for (int s = 0; s < 8; s++) {
            const int k0 = s * 16;
            uint32_t af[2][4];
            #pragma unroll
            for (int mt = 0; mt < 2; mt++) {
                const __nv_bfloat16* ap = Xs + (wm * 32 + mt * 16 + gq) * PX + k0 + 2 * tig;
                af[mt][0] = ldu32(ap);
                af[mt][1] = ldu32(ap + 8 * PX);
                af[mt][2] = ldu32(ap + 8);
                af[mt][3] = ldu32(ap + 8 * PX + 8);
            }
            #pragma unroll
            for (int nt = 0; nt < 4; nt++) {
                const __nv_bfloat16* bp = smb + WX + (wn * 32 + nt * 8 + gq) * PX + k0 + 2 * tig;
                uint32_t b0 = ldu32(bp);
                uint32_t b1 = ldu32(bp + 8);
                mma16(lin[0][nt], af[0], b0, b1);
                mma16(lin[1][nt], af[1], b0, b1);
            }
        }
        #pragma unroll
        for (int s = 0; s < 4; s++) {
            const int k0 = s * 16;
            uint32_t af[2][4];
            #pragma unroll
            for (int mt = 0; mt < 2; mt++) {
                const __nv_bfloat16* ap = Vs + (wm * 32 + mt * 16 + gq) * PV + k0 + 2 * tig;
                af[mt][0] = ldu32(ap);
                af[mt][1] = ldu32(ap + 8 * PV);
                af[mt][2] = ldu32(ap + 8);
                af[mt][3] = ldu32(ap + 8 * PV + 8);
            }
            #pragma unroll
            for (int nt = 0; nt < 4; nt++) {
                const __nv_bfloat16* bp = smb + W5 + (wn * 32 + nt * 8 + gq) * PV + k0 + 2 * tig;
                uint32_t b0 = ldu32(bp);
                uint32_t b1 = ldu32(bp + 8);
                mma16(fx[0][nt], af[0], b0, b1);
                mma16(fx[1][nt], af[1], b0, b1);
            }
        }
        __syncthreads();
        load_stage(t + 2 * stride, it & 1);

        const size_t rowBase = (size_t)t * 128;
        #pragma unroll
        for (int mt = 0; mt < 2; mt++)
            #pragma unroll
            for (int nt = 0; nt < 4; nt++) {
                const int cg = half * 128 + wn * 32 + nt * 8 + 2 * tig;
                #pragma unroll
                for (int h = 0; h < 2; h++) {
                    const size_t r = rowBase + wm * 32 + mt * 16 + gq + h * 8;
                    float v0 = sigf(fx[mt][nt][2 * h + 0] + hb5[nt][0]) * sigf(lin[mt][nt][2 * h + 0] + hbx[nt][0]);
                    float v1 = sigf(fx[mt][nt][2 * h + 1] + hb5[nt][1]) * sigf(lin[mt][nt][2 * h + 1] + hbx[nt][1]);
                    *(__nv_bfloat162*)(C + r * PH + cg) = __floats2bfloat162_rn(v0, v1);
                }
            }
    }
}

// ---------------- scan as max-plus reduction --------------------------------
__global__ void __launch_bounds__(256)
scan_part(const __nv_bfloat16* __restrict__ gate, float* __restrict__ pA, float* __restrict__ pB)
{
    const int b = blockIdx.x >> 3, c = blockIdx.x & 7;
    const int i = threadIdx.x;
    const __nv_bfloat16* gb = gate + ((size_t)b << 18);
    float Aacc = 0.f, Bacc = -3.0e38f;
    const int t0 = c * 128;
    #pragma unroll 8
    for (int t = t0; t < t0 + 128; t++) {
        float val = __bfloat162float(gb[(size_t)t * 256 + ((i + t + 1) & 255)]);
        Aacc += val;
        Bacc = fmaxf(Bacc + val, 0.f);
    }
    const int o = blockIdx.x * 256 + i;
    pA[o] = Aacc;
    pB[o] = Bacc;
}

__global__ void __launch_bounds__(256)
scan_fin(const float* __restrict__ pA, const float* __restrict__ pB,
         const float* __restrict__ Wo, const float* __restrict__ bo,
         float* __restrict__ out)
{
    const int b = blockIdx.x, i = threadIdx.x;
    float A = 0.f, B = -3.0e38f;
    #pragma unroll
    for (int c = 0; c < 8; c++) {
        const int o = (b * 8 + c) * 256 + i;
        float Ac = pA[o], Bc = pB[o];
        B = fmaxf(B + Ac, Bc);
        A += Ac;
    }
    const float v = fmaxf(A, B);
    out[PB + (size_t)b * 256 + i] = v;

    __shared__ float sh[256];
    sh[i] = v * Wo[i];
    __syncthreads();
    #pragma unroll
    for (int s = 128; s > 0; s >>= 1) {
        if (i < s) sh[i] += sh[i + s];
        __syncthreads();
    }
    if (i == 0) out[b] = 1.f / (1.f + __expf(-(sh[0] + bo[0])));
}

// ---------------- launch ---------------------------------------------------
extern "C" void kernel_launch(void* const* d_in, const int* in_sizes, int n_in,
                              void* d_out, int out_size)
{
    const float* x  = (const float*)d_in[0];
    const float* Wx = (const float*)d_in[1];
    const float* bx = (const float*)d_in[2];
    const float* W1 = (const float*)d_in[3];
    const float* b1 = (const float*)d_in[4];
    const float* W2 = (const float*)d_in[5];
    const float* b2 = (const float*)d_in[6];
    const float* W3 = (const float*)d_in[7];
    const float* b3 = (const float*)d_in[8];
    const float* W4 = (const float*)d_in[9];
    const float* b4 = (const float*)d_in[10];
    const float* W5 = (const float*)d_in[11];
    const float* b5 = (const float*)d_in[12];
    const float* Wo = (const float*)d_in[13];
    const float* bo = (const float*)d_in[14];
    float* out = (float*)d_out;

    void *p_gate, *p_xb, *p_b, *p_c, *p_pA, *p_pB;
    void *p_WxT, *p_W1T, *p_W2T, *p_W3T, *p_W4T, *p_W5T;
    void *p_b1p, *p_b2p, *p_b3p, *p_b4p;
    cudaGetSymbolAddress(&p_gate, g_gate);
    cudaGetSymbolAddress(&p_xb, g_xb);
    cudaGetSymbolAddress(&p_b, g_b);
    cudaGetSymbolAddress(&p_c, g_c);
    cudaGetSymbolAddress(&p_pA, g_pA);
    cudaGetSymbolAddress(&p_pB, g_pB);
    cudaGetSymbolAddress(&p_WxT, g_WxT);
    cudaGetSymbolAddress(&p_W1T, g_W1T);
    cudaGetSymbolAddress(&p_W2T, g_W2T);
    cudaGetSymbolAddress(&p_W3T, g_W3T);
    cudaGetSymbolAddress(&p_W4T, g_W4T);
    cudaGetSymbolAddress(&p_W5T, g_W5T);
    cudaGetSymbolAddress(&p_b1p, g_b1p);
    cudaGetSymbolAddress(&p_b2p, g_b2p);
    cudaGetSymbolAddress(&p_b3p, g_b3p);
    cudaGetSymbolAddress(&p_b4p, g_b4p);
    __nv_bfloat16* gate = (__nv_bfloat16*)p_gate;
    __nv_bfloat16* xb   = (__nv_bfloat16*)p_xb;
    __nv_bfloat16* vb   = (__nv_bfloat16*)p_b;
    __nv_bfloat16* vc   = (__nv_bfloat16*)p_c;

    // smem sizes (bytes)
    constexpr int S_F12 = (128 * 136 + 128 * 136 + 64 * 136 + 64 * 136) * 2;  // 104448
    constexpr int S_F34 = (128 * 136 + 64 * 136 + 64 * 136 + 64 * 136) * 2;   // 87040
    constexpr int S_GATE = (128 * 136 + 128 * 72 + 2 * 128 * 136 + 2 * 128 * 72) * 2;  // 159744
    cudaFuncSetAttribute(pfused<128, 128>, cudaFuncAttributeMaxDynamicSharedMemorySize, S_F12);
    cudaFuncSetAttribute(pfused<64, 64>,   cudaFuncAttributeMaxDynamicSharedMemorySize, S_F34);
    cudaFuncSetAttribute(pgate, cudaFuncAttributeMaxDynamicSharedMemorySize, S_GATE);

    prep_kernel<<<128, 256>>>(Wx, W1, b1, W2, b2, W3, b3, W4, b4, W5);
    conv_x<<<BT * 128 / (256 * 4), 256>>>(x, xb);

    // fused MLP: (L1+L2), then (L3+L4) — intermediates never leave SMEM
    pfused<128, 128><<<296, 256, S_F12>>>(xb, (const __nv_bfloat16*)p_W1T, (const float*)p_b1p,
                                          (const __nv_bfloat16*)p_W2T, (const float*)p_b2p, vb);
    pfused<64, 64><<<296, 256, S_F34>>>(vb, (const __nv_bfloat16*)p_W3T, (const float*)p_b3p,
                                        (const __nv_bfloat16*)p_W4T, (const float*)p_b4p, vc);
    // persistent fused gate
    pgate<<<dim3(2, 74), 512, S_GATE>>>(xb, (const __nv_bfloat16*)p_WxT, bx,
                                        vc, (const __nv_bfloat16*)p_W5T, b5, gate);
    // scan as parallel reduction + output head
    scan_part<<<PB * 8, 256>>>(gate, (float*)p_pA, (float*)p_pB);
    scan_fin<<<PB, 256>>>((const float*)p_pA, (const float*)p_pB, Wo, bo, out);
}